// round 7
// baseline (speedup 1.0000x reference)
#include <cuda_runtime.h>
#include <cuda_bf16.h>
#include <math.h>
#include <stdint.h>

#define N_BATCH 4
#define C_DIM   512
#define L_DIM   4096
#define NGROUP  32
#define CPG     16
#define GN_EPS  1e-5f
#define CL      ((size_t)C_DIM * L_DIM)

typedef __nv_bfloat16 bf16;

// ---------------- scratch ----------------
__device__ bf16  g_ht[N_BATCH * CL];
__device__ bf16  g_q [N_BATCH * CL];   // [L, C], pre-scaled by att_scale
__device__ bf16  g_k [N_BATCH * CL];   // [L, C]
__device__ bf16  g_v [N_BATCH * CL];   // [C, L]
__device__ bf16  g_o [N_BATCH * CL];   // [L, C]
__device__ bf16  g_wq[C_DIM * C_DIM];
__device__ bf16  g_wk[C_DIM * C_DIM];
__device__ bf16  g_wv[C_DIM * C_DIM];
__device__ bf16  g_wo[C_DIM * C_DIM];

__global__ void cvt_w_kernel(const float* __restrict__ wq, const float* __restrict__ wk,
                             const float* __restrict__ wv, const float* __restrict__ wo)
{
    int i = blockIdx.x * 256 + threadIdx.x;
    g_wq[i] = __float2bfloat16(wq[i]);
    g_wk[i] = __float2bfloat16(wk[i]);
    g_wv[i] = __float2bfloat16(wv[i]);
    g_wo[i] = __float2bfloat16(wo[i]);
}

// ---------------- GroupNorm -> h_t[L, C] bf16 (512 threads) ----------------
__global__ __launch_bounds__(512) void gn_kernel(const float* __restrict__ x,
                                                 const float* __restrict__ scale,
                                                 const float* __restrict__ bias,
                                                 bf16* __restrict__ ht)
{
    const int n = blockIdx.x >> 5;
    const int g = blockIdx.x & 31;
    const float* __restrict__ xg = x + ((size_t)n * C_DIM + (size_t)g * CPG) * L_DIM;
    bf16* __restrict__ hb = ht + (size_t)n * CL + g * CPG;
    const int tid = threadIdx.x;

    const float4* xv = (const float4*)xg;
    float s = 0.f, ss = 0.f;
    for (int i = tid; i < CPG * L_DIM / 4; i += 512) {
        float4 v = xv[i];
        s  += v.x + v.y + v.z + v.w;
        ss += v.x*v.x + v.y*v.y + v.z*v.z + v.w*v.w;
    }
    __shared__ float rs[512], rss[512];
    rs[tid] = s; rss[tid] = ss;
    __syncthreads();
    for (int st = 256; st > 0; st >>= 1) {
        if (tid < st) { rs[tid] += rs[tid+st]; rss[tid] += rss[tid+st]; }
        __syncthreads();
    }
    const float inv_n = 1.f / (float)(CPG * L_DIM);
    const float mean = rs[0] * inv_n;
    const float var  = rss[0] * inv_n - mean * mean;
    const float rstd = rsqrtf(var + GN_EPS);

    __shared__ float tile[16][260];
    for (int l0 = 0; l0 < L_DIM; l0 += 256) {
        #pragma unroll
        for (int j = 0; j < 2; j++) {
            int vi = tid + j * 512;
            int c  = vi >> 6;
            int lv = vi & 63;
            float4 v = xv[c * (L_DIM/4) + (l0 >> 2) + lv];
            float sc = scale[g*CPG + c] * rstd;
            float bi = bias[g*CPG + c] - mean * sc;
            tile[c][4*lv+0] = v.x*sc + bi;
            tile[c][4*lv+1] = v.y*sc + bi;
            tile[c][4*lv+2] = v.z*sc + bi;
            tile[c][4*lv+3] = v.w*sc + bi;
        }
        __syncthreads();
        #pragma unroll
        for (int j = 0; j < 2; j++) {
            int vi = tid + j * 512;
            int l  = vi >> 2;
            int c4 = vi & 3;
            __nv_bfloat162 p0 = __floats2bfloat162_rn(tile[4*c4+0][l], tile[4*c4+1][l]);
            __nv_bfloat162 p1 = __floats2bfloat162_rn(tile[4*c4+2][l], tile[4*c4+3][l]);
            bf16* dst = hb + (size_t)(l0 + l) * C_DIM + 4*c4;
            *(__nv_bfloat162*)(dst)     = p0;
            *(__nv_bfloat162*)(dst + 2) = p1;
        }
        __syncthreads();
    }
}

// ---------------- common MMA helpers ----------------
__device__ __forceinline__ void mma_bf16(float* d, const uint32_t* a, const uint32_t* b) {
    asm volatile(
        "mma.sync.aligned.m16n8k16.row.col.f32.bf16.bf16.f32 "
        "{%0,%1,%2,%3},{%4,%5,%6,%7},{%8,%9},{%0,%1,%2,%3};"
        : "+f"(d[0]), "+f"(d[1]), "+f"(d[2]), "+f"(d[3])
        : "r"(a[0]), "r"(a[1]), "r"(a[2]), "r"(a[3]), "r"(b[0]), "r"(b[1]));
}

__device__ __forceinline__ void ldsm_x4(uint32_t* r, uint32_t addr) {
    asm volatile("ldmatrix.sync.aligned.m8n8.x4.shared.b16 {%0,%1,%2,%3}, [%4];"
        : "=r"(r[0]), "=r"(r[1]), "=r"(r[2]), "=r"(r[3]) : "r"(addr));
}

#define CP16(dst, src) asm volatile("cp.async.cg.shared.global [%0], [%1], 16;" :: "r"(dst), "l"(src))
#define CP_COMMIT()    asm volatile("cp.async.commit_group;")
#define CP_WAIT(n)     asm volatile("cp.async.wait_group %0;" :: "n"(n))

// ================= fused QKV projection (R4-proven GEMM config) =================
#define BM 128
#define BN 128
#define PITCH 72
#define TILEE (128 * PITCH)
#define SMEM_BYTES (4 * TILEE * 2)     // 73728 B

__global__ __launch_bounds__(256, 2)
void qkv_kernel(const bf16* __restrict__ ht,
                float att_scale,
                const float* __restrict__ bq, const float* __restrict__ bk,
                const float* __restrict__ bv)
{
    extern __shared__ bf16 sm[];
    const int which = blockIdx.z >> 2;   // 0 q, 1 k, 2 v
    const int nb    = blockIdx.z & 3;
    const bf16* A = ht + (size_t)nb * CL;
    const bf16* B = (which == 0) ? g_wq : (which == 1) ? g_wk : g_wv;
    const float* bias = (which == 0) ? bq : (which == 1) ? bk : bv;

    const int tid = threadIdx.x;
    const int bm = blockIdx.y * BM;
    const int bn = blockIdx.x * BN;
    const int lane = tid & 31;
    const int warp = tid >> 5;
    const int wm   = (warp >> 2) << 6;
    const int wn   = (warp & 3) << 5;
    const int gid  = lane >> 2;
    const int tig  = lane & 3;

    const uint32_t smem_u = (uint32_t)__cvta_generic_to_shared(sm);
    const uint32_t a_off = ((wm + (lane & 15)) * PITCH + ((lane >> 4) << 3)) * 2;
    const uint32_t b_off = ((wn + (lane & 7) + ((lane >> 4) << 3)) * PITCH
                            + (((lane >> 3) & 1) << 3)) * 2;

    float acc[4][4][4];
    #pragma unroll
    for (int i = 0; i < 4; i++)
        #pragma unroll
        for (int j = 0; j < 4; j++)
            #pragma unroll
            for (int r = 0; r < 4; r++) acc[i][j][r] = 0.f;

    auto load_tiles = [&](int k0, int s) {
        bf16* As = sm + s * TILEE;
        bf16* Bs = sm + (2 + s) * TILEE;
        #pragma unroll
        for (int i = 0; i < 4; i++) {
            int id  = tid + i * 256;
            int row = id >> 3;
            int cof = (id & 7) << 3;
            CP16((uint32_t)__cvta_generic_to_shared(As + row * PITCH + cof),
                 A + (size_t)(bm + row) * C_DIM + k0 + cof);
            CP16((uint32_t)__cvta_generic_to_shared(Bs + row * PITCH + cof),
                 B + (size_t)(bn + row) * C_DIM + k0 + cof);
        }
    };

    load_tiles(0, 0);
    CP_COMMIT();

    int s = 0;
    #pragma unroll 1
    for (int it = 0; it < C_DIM / 64; it++) {
        CP_WAIT(0);
        __syncthreads();
        if (it + 1 < C_DIM / 64) {
            load_tiles((it + 1) << 6, s ^ 1);
            CP_COMMIT();
        }
        const uint32_t As_u = smem_u + s * (TILEE * 2);
        const uint32_t Bs_u = smem_u + (2 + s) * (TILEE * 2);
        #pragma unroll
        for (int ks = 0; ks < 4; ks++) {
            const uint32_t kadd = ks * 32;
            uint32_t a[4][4], b[4][2];
            #pragma unroll
            for (int mt = 0; mt < 4; mt++)
                ldsm_x4(a[mt], As_u + a_off + mt * (16 * PITCH * 2) + kadd);
            #pragma unroll
            for (int p = 0; p < 2; p++) {
                uint32_t r[4];
                ldsm_x4(r, Bs_u + b_off + p * (16 * PITCH * 2) + kadd);
                b[2*p][0]   = r[0]; b[2*p][1]   = r[1];
                b[2*p+1][0] = r[2]; b[2*p+1][1] = r[3];
            }
            #pragma unroll
            for (int mt = 0; mt < 4; mt++)
                #pragma unroll
                for (int nt = 0; nt < 4; nt++)
                    mma_bf16(acc[mt][nt], a[mt], b[nt]);
        }
        s ^= 1;
    }

    if (which <= 1) {
        const float scl = (which == 0) ? att_scale : 1.f;
        bf16* C = ((which == 0) ? g_q : g_k) + (size_t)nb * CL;
        #pragma unroll
        for (int mt = 0; mt < 4; mt++) {
            #pragma unroll
            for (int nt = 0; nt < 4; nt++) {
                int m0 = bm + wm + mt * 16 + gid;
                int n0 = bn + wn + nt * 8 + 2 * tig;
                float b0 = bias[n0], b1 = bias[n0 + 1];
                float d0 = (acc[mt][nt][0] + b0) * scl;
                float d1 = (acc[mt][nt][1] + b1) * scl;
                float d2 = (acc[mt][nt][2] + b0) * scl;
                float d3 = (acc[mt][nt][3] + b1) * scl;
                *(__nv_bfloat162*)&C[(size_t)m0 * C_DIM + n0]       = __floats2bfloat162_rn(d0, d1);
                *(__nv_bfloat162*)&C[(size_t)(m0 + 8) * C_DIM + n0] = __floats2bfloat162_rn(d2, d3);
            }
        }
    } else {
        // v: transposed store to [C, L] via smem staging
        bf16* smh = sm;
        __syncthreads();
        #pragma unroll
        for (int mt = 0; mt < 4; mt++) {
            #pragma unroll
            for (int nt = 0; nt < 4; nt++) {
                int ml = wm + mt * 16 + gid;
                int nl = wn + nt * 8 + 2 * tig;
                int n0 = bn + nl;
                float b0 = bias[n0], b1 = bias[n0 + 1];
                smh[nl * 136 + ml]           = __float2bfloat16(acc[mt][nt][0] + b0);
                smh[(nl + 1) * 136 + ml]     = __float2bfloat16(acc[mt][nt][1] + b1);
                smh[nl * 136 + ml + 8]       = __float2bfloat16(acc[mt][nt][2] + b0);
                smh[(nl + 1) * 136 + ml + 8] = __float2bfloat16(acc[mt][nt][3] + b1);
            }
        }
        __syncthreads();
        bf16* C = g_v + (size_t)nb * CL;
        #pragma unroll
        for (int i = 0; i < 8; i++) {
            int idx = tid + i * 256;
            int row = idx >> 4;
            int m = (idx & 15) << 3;
            uint4 v = *(uint4*)&smh[row * 136 + m];
            *(uint4*)&C[(size_t)(bn + row) * L_DIM + bm + m] = v;
        }
    }
}

// ================= final projection: out = (O x wo^T)^T + bo + x =================
__global__ __launch_bounds__(256, 2)
void final_kernel(const bf16* __restrict__ Ag, float* __restrict__ Cg,
                  const float* __restrict__ bias, const float* __restrict__ resg)
{
    extern __shared__ bf16 sm[];
    const int tid = threadIdx.x;
    const int bm = blockIdx.y * BM;
    const int bn = blockIdx.x * BN;
    const bf16* A = Ag + (size_t)blockIdx.z * CL;
    const bf16* B = g_wo;
    const float* R = resg + (size_t)blockIdx.z * CL;
    float* C = Cg + (size_t)blockIdx.z * CL;

    const int lane = tid & 31;
    const int warp = tid >> 5;
    const int wm   = (warp >> 2) << 6;
    const int wn   = (warp & 3) << 5;
    const int gid  = lane >> 2;
    const int tig  = lane & 3;

    const uint32_t smem_u = (uint32_t)__cvta_generic_to_shared(sm);
    const uint32_t a_off = ((wm + (lane & 15)) * PITCH + ((lane >> 4) << 3)) * 2;
    const uint32_t b_off = ((wn + (lane & 7) + ((lane >> 4) << 3)) * PITCH
                            + (((lane >> 3) & 1) << 3)) * 2;

    float acc[4][4][4];
    #pragma unroll
    for (int i = 0; i < 4; i++)
        #pragma unroll
        for (int j = 0; j < 4; j++)
            #pragma unroll
            for (int r = 0; r < 4; r++) acc[i][j][r] = 0.f;

    auto load_tiles = [&](int k0, int s) {
        bf16* As = sm + s * TILEE;
        bf16* Bs = sm + (2 + s) * TILEE;
        #pragma unroll
        for (int i = 0; i < 4; i++) {
            int id  = tid + i * 256;
            int row = id >> 3;
            int cof = (id & 7) << 3;
            CP16((uint32_t)__cvta_generic_to_shared(As + row * PITCH + cof),
                 A + (size_t)(bm + row) * C_DIM + k0 + cof);
            CP16((uint32_t)__cvta_generic_to_shared(Bs + row * PITCH + cof),
                 B + (size_t)(bn + row) * C_DIM + k0 + cof);
        }
    };

    load_tiles(0, 0);
    CP_COMMIT();

    int s = 0;
    #pragma unroll 1
    for (int it = 0; it < C_DIM / 64; it++) {
        CP_WAIT(0);
        __syncthreads();
        if (it + 1 < C_DIM / 64) {
            load_tiles((it + 1) << 6, s ^ 1);
            CP_COMMIT();
        }
        const uint32_t As_u = smem_u + s * (TILEE * 2);
        const uint32_t Bs_u = smem_u + (2 + s) * (TILEE * 2);
        #pragma unroll
        for (int ks = 0; ks < 4; ks++) {
            const uint32_t kadd = ks * 32;
            uint32_t a[4][4], b[4][2];
            #pragma unroll
            for (int mt = 0; mt < 4; mt++)
                ldsm_x4(a[mt], As_u + a_off + mt * (16 * PITCH * 2) + kadd);
            #pragma unroll
            for (int p = 0; p < 2; p++) {
                uint32_t r[4];
                ldsm_x4(r, Bs_u + b_off + p * (16 * PITCH * 2) + kadd);
                b[2*p][0]   = r[0]; b[2*p][1]   = r[1];
                b[2*p+1][0] = r[2]; b[2*p+1][1] = r[3];
            }
            #pragma unroll
            for (int mt = 0; mt < 4; mt++)
                #pragma unroll
                for (int nt = 0; nt < 4; nt++)
                    mma_bf16(acc[mt][nt], a[mt], b[nt]);
        }
        s ^= 1;
    }

    // fp32 transposed + bias + residual via smem staging
    float* smf = (float*)sm;
    __syncthreads();
    #pragma unroll
    for (int mt = 0; mt < 4; mt++) {
        #pragma unroll
        for (int nt = 0; nt < 4; nt++) {
            int ml = wm + mt * 16 + gid;
            int nl = wn + nt * 8 + 2 * tig;
            int n0 = bn + nl;
            float b0 = bias[n0], b1 = bias[n0 + 1];
            smf[nl * 132 + ml]           = acc[mt][nt][0] + b0;
            smf[(nl + 1) * 132 + ml]     = acc[mt][nt][1] + b1;
            smf[nl * 132 + ml + 8]       = acc[mt][nt][2] + b0;
            smf[(nl + 1) * 132 + ml + 8] = acc[mt][nt][3] + b1;
        }
    }
    __syncthreads();
    #pragma unroll
    for (int i = 0; i < 16; i++) {
        int idx = tid + i * 256;
        int row = idx >> 5;
        int m = (idx & 31) << 2;
        size_t gidx = (size_t)(bn + row) * L_DIM + bm + m;
        float4 v = *(float4*)&smf[row * 132 + m];
        float4 r4 = *(const float4*)&R[gidx];
        v.x += r4.x; v.y += r4.y; v.z += r4.z; v.w += r4.w;
        *(float4*)&C[gidx] = v;
    }
}

// ================= flash attention =================
// grid (64 qblocks, N_BATCH); 256 threads (8 warps); 1 CTA/SM.
// S layout: 2x4 warps, warp [32,16]. O layout: 1x8, warp [64 rows, 64 cols].
#define FQP 520                       // Q/K smem pitch (bf16)
#define F_OFF_Q  0
#define F_OFF_K  66560
#define F_OFF_V  133120
#define F_VSTAGE 36864                // 256 slots x 72 x 2B
#define F_OFF_P  206848               // 64 x 72 x 2B = 9216
#define F_OFF_ST 216064
#define F_SMEM   219136

__global__ __launch_bounds__(256, 1)
void flash_kernel(const bf16* __restrict__ qg, const bf16* __restrict__ kg,
                  const bf16* __restrict__ vg, bf16* __restrict__ og)
{
    extern __shared__ char smc[];
    const uint32_t su = (uint32_t)__cvta_generic_to_shared(smc);
    const int tid = threadIdx.x, warp = tid >> 5, lane = tid & 31;
    const int gid = lane >> 2, tig = lane & 3;
    const int wr = warp >> 2, wc = warp & 3;
    const int qrow0 = blockIdx.x << 6;
    const bf16* q = qg + (size_t)blockIdx.y * CL;
    const bf16* k = kg + (size_t)blockIdx.y * CL;
    const bf16* v = vg + (size_t)blockIdx.y * CL;
    bf16* o = og + (size_t)blockIdx.y * CL;

    float* m_s     = (float*)(smc + F_OFF_ST);      // [64]
    float* l_s     = m_s + 64;                      // [64]
    float* alpha_s = m_s + 128;                     // [64]
    float* wmax    = m_s + 192;                     // [4][64]
    float* wsum    = m_s + 448;                     // [4][64]
    bf16*  Pt      = (bf16*)(smc + F_OFF_P);

    auto load_qk = [&](uint32_t off, const bf16* base, int row0) {
        #pragma unroll
        for (int t = 0; t < 16; t++) {
            int idx = tid + t * 256;
            int row = idx >> 6, co = (idx & 63) << 3;
            CP16(su + off + (uint32_t)(row * FQP + co) * 2,
                 base + (size_t)(row0 + row) * C_DIM + co);
        }
    };
    auto load_v = [&](int jb, int s) {
        #pragma unroll
        for (int t = 0; t < 8; t++) {
            int idx = tid + t * 256;
            int slot = idx >> 3, co = (idx & 7) << 3;
            int c = ((slot >> 5) << 6) + s * 32 + (slot & 31);
            CP16(su + F_OFF_V + s * F_VSTAGE + (uint32_t)(slot * 72 + co) * 2,
                 v + (size_t)c * L_DIM + jb + co);
        }
    };

    if (tid < 64) { m_s[tid] = -1e30f; l_s[tid] = 0.f; }

    load_qk(F_OFF_Q, q, qrow0); CP_COMMIT();
    load_qk(F_OFF_K, k, 0);     CP_COMMIT();
    load_v(0, 0);               CP_COMMIT();

    const uint32_t aS = su + F_OFF_Q +
        (uint32_t)(((wr * 32 + (lane & 15)) * FQP + ((lane >> 4) << 3)) * 2);
    const uint32_t bS = su + F_OFF_K +
        (uint32_t)(((wc * 16 + (lane & 7) + ((lane >> 4) << 3)) * FQP + (((lane >> 3) & 1) << 3)) * 2);
    const uint32_t aO = su + F_OFF_P +
        (uint32_t)((((lane & 15)) * 72 + ((lane >> 4) << 3)) * 2);
    const uint32_t bO = su + F_OFF_V +
        (uint32_t)(((warp * 32 + (lane & 7) + ((lane >> 4) << 3)) * 72 + (((lane >> 3) & 1) << 3)) * 2);

    float accO[4][8][4] = {};

    #pragma unroll 1
    for (int j = 0; j < 64; j++) {
        const int jb  = j << 6;
        const int jbn = ((j + 1 < 64) ? (j + 1) : 63) << 6;

        CP_WAIT(1);                    // K(j) ready
        __syncthreads();               // B1

        float mold[2][2];
        #pragma unroll
        for (int mt = 0; mt < 2; mt++)
            #pragma unroll
            for (int r = 0; r < 2; r++)
                mold[mt][r] = m_s[wr * 32 + mt * 16 + gid + r * 8];

        load_v(jb, 1); CP_COMMIT();    // Vs1(j)

        // ---- S = Q' K^T ----
        float sc[2][2][4] = {};
        #pragma unroll 8
        for (int ks = 0; ks < 32; ks++) {
            uint32_t a0[4], a1[4], bt[4];
            ldsm_x4(a0, aS + ks * 32);
            ldsm_x4(a1, aS + 16 * FQP * 2 + ks * 32);
            ldsm_x4(bt, bS + ks * 32);
            uint32_t b0[2] = {bt[0], bt[1]}, b1[2] = {bt[2], bt[3]};
            mma_bf16(sc[0][0], a0, b0); mma_bf16(sc[0][1], a0, b1);
            mma_bf16(sc[1][0], a1, b0); mma_bf16(sc[1][1], a1, b1);
        }

        // ---- online softmax ----
        #pragma unroll
        for (int mt = 0; mt < 2; mt++)
            #pragma unroll
            for (int r = 0; r < 2; r++) {
                float vmx = fmaxf(fmaxf(sc[mt][0][2*r], sc[mt][0][2*r+1]),
                                  fmaxf(sc[mt][1][2*r], sc[mt][1][2*r+1]));
                vmx = fmaxf(vmx, __shfl_xor_sync(0xffffffffu, vmx, 1));
                vmx = fmaxf(vmx, __shfl_xor_sync(0xffffffffu, vmx, 2));
                if (tig == 0) wmax[wc * 64 + wr * 32 + mt * 16 + gid + r * 8] = vmx;
            }
        __syncthreads();               // B2a

        float mnew[2][2], al[2][2], rsum[2][2];
        #pragma unroll
        for (int mt = 0; mt < 2; mt++)
            #pragma unroll
            for (int r = 0; r < 2; r++) {
                int row = wr * 32 + mt * 16 + gid + r * 8;
                float mm = mold[mt][r];
                mm = fmaxf(mm, wmax[row]);
                mm = fmaxf(mm, wmax[64 + row]);
                mm = fmaxf(mm, wmax[128 + row]);
                mm = fmaxf(mm, wmax[192 + row]);
                mnew[mt][r] = mm;
                al[mt][r] = __expf(mold[mt][r] - mm);
                rsum[mt][r] = 0.f;
            }
        #pragma unroll
        for (int mt = 0; mt < 2; mt++)
            #pragma unroll
            for (int nt = 0; nt < 2; nt++)
                #pragma unroll
                for (int e = 0; e < 4; e++) {
                    int r = e >> 1;
                    sc[mt][nt][e] = __expf(sc[mt][nt][e] - mnew[mt][r]);
                    rsum[mt][r] += sc[mt][nt][e];
                }
        #pragma unroll
        for (int mt = 0; mt < 2; mt++)
            #pragma unroll
            for (int r = 0; r < 2; r++) {
                float sv = rsum[mt][r];
                sv += __shfl_xor_sync(0xffffffffu, sv, 1);
                sv += __shfl_xor_sync(0xffffffffu, sv, 2);
                rsum[mt][r] = sv;
                int row = wr * 32 + mt * 16 + gid + r * 8;
                if (tig == 0) wsum[wc * 64 + row] = sv;
                if (wc == 0 && tig == 0) { alpha_s[row] = al[mt][r]; m_s[row] = mnew[mt][r]; }
            }
        // P -> smem bf16
        #pragma unroll
        for (int mt = 0; mt < 2; mt++)
            #pragma unroll
            for (int r = 0; r < 2; r++)
                #pragma unroll
                for (int nt = 0; nt < 2; nt++) {
                    int row = wr * 32 + mt * 16 + gid + r * 8;
                    int col = wc * 16 + nt * 8 + 2 * tig;
                    *(__nv_bfloat162*)(Pt + row * 72 + col) =
                        __floats2bfloat162_rn(sc[mt][nt][2*r], sc[mt][nt][2*r+1]);
                }
        __syncthreads();               // B2b

        if (wc == 0 && tig == 0) {
            #pragma unroll
            for (int mt = 0; mt < 2; mt++)
                #pragma unroll
                for (int r = 0; r < 2; r++) {
                    int row = wr * 32 + mt * 16 + gid + r * 8;
                    l_s[row] = l_s[row] * al[mt][r]
                             + wsum[row] + wsum[64 + row] + wsum[128 + row] + wsum[192 + row];
                }
        }

        load_qk(F_OFF_K, k, jbn); CP_COMMIT();   // K(j+1)

        // ---- O rescale ----
        float a8[4][2];
        #pragma unroll
        for (int mt = 0; mt < 4; mt++)
            #pragma unroll
            for (int r = 0; r < 2; r++)
                a8[mt][r] = alpha_s[mt * 16 + gid + r * 8];
        #pragma unroll
        for (int mt = 0; mt < 4; mt++)
            #pragma unroll
            for (int j8 = 0; j8 < 8; j8++)
                #pragma unroll
                for (int e = 0; e < 4; e++)
                    accO[mt][j8][e] *= a8[mt][e >> 1];

        CP_WAIT(2);                    // Vs0(j) ready
        __syncthreads();               // B3

        // ---- O += P V, stage 0 ----
        #pragma unroll
        for (int ks = 0; ks < 4; ks++) {
            uint32_t a[4][4], bt0[4], bt1[4];
            #pragma unroll
            for (int mt = 0; mt < 4; mt++)
                ldsm_x4(a[mt], aO + mt * (16 * 72 * 2) + ks * 32);
            ldsm_x4(bt0, bO + ks * 32);
            ldsm_x4(bt1, bO + 16 * 72 * 2 + ks * 32);
            uint32_t b0[2] = {bt0[0], bt0[1]}, b1[2] = {bt0[2], bt0[3]};
            uint32_t b2[2] = {bt1[0], bt1[1]}, b3[2] = {bt1[2], bt1[3]};
            #pragma unroll
            for (int mt = 0; mt < 4; mt++) {
                mma_bf16(accO[mt][0], a[mt], b0);
                mma_bf16(accO[mt][1], a[mt], b1);
                mma_bf16(accO[mt][2], a[mt], b2);
                mma_bf16(accO[mt][3], a[mt], b3);
            }
        }
        __syncthreads();               // B4
        load_v(jbn, 0); CP_COMMIT();   // Vs0(j+1)
        CP_WAIT(2);                    // Vs1(j) ready
        __syncthreads();               // B5

        // ---- O += P V, stage 1 ----
        #pragma unroll
        for (int ks = 0; ks < 4; ks++) {
            uint32_t a[4][4], bt0[4], bt1[4];
            #pragma unroll
            for (int mt = 0; mt < 4; mt++)
                ldsm_x4(a[mt], aO + mt * (16 * 72 * 2) + ks * 32);
            ldsm_x4(bt0, bO + F_VSTAGE + ks * 32);
            ldsm_x4(bt1, bO + F_VSTAGE + 16 * 72 * 2 + ks * 32);
            uint32_t b0[2] = {bt0[0], bt0[1]}, b1[2] = {bt0[2], bt0[3]};
            uint32_t b2[2] = {bt1[0], bt1[1]}, b3[2] = {bt1[2], bt1[3]};
            #pragma unroll
            for (int mt = 0; mt < 4; mt++) {
                mma_bf16(accO[mt][4], a[mt], b0);
                mma_bf16(accO[mt][5], a[mt], b1);
                mma_bf16(accO[mt][6], a[mt], b2);
                mma_bf16(accO[mt][7], a[mt], b3);
            }
        }
    }

    CP_WAIT(0);
    __syncthreads();

    // ---- normalize + store ----
    float il[4][2];
    #pragma unroll
    for (int mt = 0; mt < 4; mt++)
        #pragma unroll
        for (int r = 0; r < 2; r++)
            il[mt][r] = 1.f / l_s[mt * 16 + gid + r * 8];
    #pragma unroll
    for (int mt = 0; mt < 4; mt++) {
        #pragma unroll
        for (int j8 = 0; j8 < 8; j8++) {
            int col = warp * 64 + j8 * 8 + 2 * tig;
            int row0 = qrow0 + mt * 16 + gid;
            *(__nv_bfloat162*)(o + (size_t)row0 * C_DIM + col) =
                __floats2bfloat162_rn(accO[mt][j8][0] * il[mt][0], accO[mt][j8][1] * il[mt][0]);
            *(__nv_bfloat162*)(o + (size_t)(row0 + 8) * C_DIM + col) =
                __floats2bfloat162_rn(accO[mt][j8][2] * il[mt][1], accO[mt][j8][3] * il[mt][1]);
        }
    }
}

// ---------------- host launch ----------------
extern "C" void kernel_launch(void* const* d_in, const int* in_sizes, int n_in,
                              void* d_out, int out_size)
{
    const float* x        = (const float*)d_in[0];
    const float* gn_scale = (const float*)d_in[1];
    const float* gn_bias  = (const float*)d_in[2];
    const float* wq = (const float*)d_in[3];
    const float* bq = (const float*)d_in[4];
    const float* wk = (const float*)d_in[5];
    const float* bk = (const float*)d_in[6];
    const float* wv = (const float*)d_in[7];
    const float* bv = (const float*)d_in[8];
    const float* wo = (const float*)d_in[9];
    const float* bo = (const float*)d_in[10];
    float* out = (float*)d_out;

    static bf16 *p_ht=nullptr, *p_q=nullptr, *p_k=nullptr, *p_v=nullptr, *p_o=nullptr;
    if (!p_ht) {
        cudaGetSymbolAddress((void**)&p_ht, g_ht);
        cudaGetSymbolAddress((void**)&p_q,  g_q);
        cudaGetSymbolAddress((void**)&p_k,  g_k);
        cudaGetSymbolAddress((void**)&p_v,  g_v);
        cudaGetSymbolAddress((void**)&p_o,  g_o);
        cudaFuncSetAttribute(qkv_kernel,   cudaFuncAttributeMaxDynamicSharedMemorySize, SMEM_BYTES);
        cudaFuncSetAttribute(final_kernel, cudaFuncAttributeMaxDynamicSharedMemorySize, SMEM_BYTES);
        cudaFuncSetAttribute(flash_kernel, cudaFuncAttributeMaxDynamicSharedMemorySize, F_SMEM);
    }

    const float att_scale = 0.044194173824159216f;   // 512^-0.5

    cvt_w_kernel<<<(C_DIM * C_DIM) / 256, 256>>>(wq, wk, wv, wo);
    gn_kernel<<<N_BATCH * NGROUP, 512>>>(x, gn_scale, gn_bias, p_ht);

    dim3 gq(C_DIM / BN, L_DIM / BM, 3 * N_BATCH);   // (4, 32, 12)
    qkv_kernel<<<gq, 256, SMEM_BYTES>>>(p_ht, att_scale, bq, bk, bv);

    dim3 gf(L_DIM / 64, N_BATCH);                   // (64, 4)
    flash_kernel<<<gf, 256, F_SMEM>>>(p_q, p_k, p_v, p_o);

    dim3 go(C_DIM / BN, L_DIM / BM, N_BATCH);       // (4, 32, 4)
    final_kernel<<<go, 256, SMEM_BYTES>>>(p_o, out, bo, x);
}

// round 8
// speedup vs baseline: 1.2758x; 1.2758x over previous
#include <cuda_runtime.h>
#include <cuda_bf16.h>
#include <math.h>
#include <stdint.h>

#define N_BATCH 4
#define C_DIM   512
#define L_DIM   4096
#define NGROUP  32
#define CPG     16
#define GN_EPS  1e-5f
#define CL      ((size_t)C_DIM * L_DIM)
#define LL      ((size_t)L_DIM * L_DIM)

typedef __nv_bfloat16 bf16;

// ---------------- scratch ----------------
__device__ bf16  g_ht[N_BATCH * CL];
__device__ bf16  g_q [N_BATCH * CL];       // [L, C], pre-scaled by att_scale
__device__ bf16  g_k [N_BATCH * CL];       // [L, C]
__device__ bf16  g_v [N_BATCH * CL];       // [C, L]
__device__ bf16  g_o [N_BATCH * CL];       // [L, C]
__device__ bf16  g_p [N_BATCH * LL];       // unnormalized exp(scores), bf16
__device__ float g_psum[N_BATCH * L_DIM * 32];  // per-(row, ntile) partial sums
__device__ float g_rowsum[N_BATCH * L_DIM];
__device__ bf16  g_wq[C_DIM * C_DIM];
__device__ bf16  g_wk[C_DIM * C_DIM];
__device__ bf16  g_wv[C_DIM * C_DIM];
__device__ bf16  g_wo[C_DIM * C_DIM];

__global__ void cvt_w_kernel(const float* __restrict__ wq, const float* __restrict__ wk,
                             const float* __restrict__ wv, const float* __restrict__ wo)
{
    int i = blockIdx.x * 256 + threadIdx.x;
    g_wq[i] = __float2bfloat16(wq[i]);
    g_wk[i] = __float2bfloat16(wk[i]);
    g_wv[i] = __float2bfloat16(wv[i]);
    g_wo[i] = __float2bfloat16(wo[i]);
}

// ---------------- GroupNorm -> h_t[L, C] bf16 (512 threads) ----------------
__global__ __launch_bounds__(512) void gn_kernel(const float* __restrict__ x,
                                                 const float* __restrict__ scale,
                                                 const float* __restrict__ bias,
                                                 bf16* __restrict__ ht)
{
    const int n = blockIdx.x >> 5;
    const int g = blockIdx.x & 31;
    const float* __restrict__ xg = x + ((size_t)n * C_DIM + (size_t)g * CPG) * L_DIM;
    bf16* __restrict__ hb = ht + (size_t)n * CL + g * CPG;
    const int tid = threadIdx.x;

    const float4* xv = (const float4*)xg;
    float s = 0.f, ss = 0.f;
    for (int i = tid; i < CPG * L_DIM / 4; i += 512) {
        float4 v = xv[i];
        s  += v.x + v.y + v.z + v.w;
        ss += v.x*v.x + v.y*v.y + v.z*v.z + v.w*v.w;
    }
    __shared__ float rs[512], rss[512];
    rs[tid] = s; rss[tid] = ss;
    __syncthreads();
    for (int st = 256; st > 0; st >>= 1) {
        if (tid < st) { rs[tid] += rs[tid+st]; rss[tid] += rss[tid+st]; }
        __syncthreads();
    }
    const float inv_n = 1.f / (float)(CPG * L_DIM);
    const float mean = rs[0] * inv_n;
    const float var  = rss[0] * inv_n - mean * mean;
    const float rstd = rsqrtf(var + GN_EPS);

    __shared__ float tile[16][260];
    for (int l0 = 0; l0 < L_DIM; l0 += 256) {
        #pragma unroll
        for (int j = 0; j < 2; j++) {
            int vi = tid + j * 512;
            int c  = vi >> 6;
            int lv = vi & 63;
            float4 v = xv[c * (L_DIM/4) + (l0 >> 2) + lv];
            float sc = scale[g*CPG + c] * rstd;
            float bi = bias[g*CPG + c] - mean * sc;
            tile[c][4*lv+0] = v.x*sc + bi;
            tile[c][4*lv+1] = v.y*sc + bi;
            tile[c][4*lv+2] = v.z*sc + bi;
            tile[c][4*lv+3] = v.w*sc + bi;
        }
        __syncthreads();
        #pragma unroll
        for (int j = 0; j < 2; j++) {
            int vi = tid + j * 512;
            int l  = vi >> 2;
            int c4 = vi & 3;
            __nv_bfloat162 p0 = __floats2bfloat162_rn(tile[4*c4+0][l], tile[4*c4+1][l]);
            __nv_bfloat162 p1 = __floats2bfloat162_rn(tile[4*c4+2][l], tile[4*c4+3][l]);
            bf16* dst = hb + (size_t)(l0 + l) * C_DIM + 4*c4;
            *(__nv_bfloat162*)(dst)     = p0;
            *(__nv_bfloat162*)(dst + 2) = p1;
        }
        __syncthreads();
    }
}

// ---------------- common MMA helpers ----------------
__device__ __forceinline__ void mma_bf16(float* d, const uint32_t* a, const uint32_t* b) {
    asm volatile(
        "mma.sync.aligned.m16n8k16.row.col.f32.bf16.bf16.f32 "
        "{%0,%1,%2,%3},{%4,%5,%6,%7},{%8,%9},{%0,%1,%2,%3};"
        : "+f"(d[0]), "+f"(d[1]), "+f"(d[2]), "+f"(d[3])
        : "r"(a[0]), "r"(a[1]), "r"(a[2]), "r"(a[3]), "r"(b[0]), "r"(b[1]));
}

__device__ __forceinline__ void ldsm_x4(uint32_t* r, uint32_t addr) {
    asm volatile("ldmatrix.sync.aligned.m8n8.x4.shared.b16 {%0,%1,%2,%3}, [%4];"
        : "=r"(r[0]), "=r"(r[1]), "=r"(r[2]), "=r"(r[3]) : "r"(addr));
}

#define CP16(dst, src) asm volatile("cp.async.cg.shared.global [%0], [%1], 16;" :: "r"(dst), "l"(src))
#define CP_COMMIT()    asm volatile("cp.async.commit_group;")
#define CP_WAIT(n)     asm volatile("cp.async.wait_group %0;" :: "n"(n))

#define BM 128
#define BN 128
#define PITCH 72
#define TILEE (128 * PITCH)
#define SMEM_BYTES (4 * TILEE * 2)     // 73728 B

// Shared mainloop: loads A[M,K],B[N,K] K-major bf16 tiles, accumulates acc[4][4][4].
// warp layout: wm=(warp>>2)*64, wn=(warp&3)*32 (R4-proven).
#define GEMM_MAINLOOP(A, B, K)                                                      \
    const uint32_t smem_u = (uint32_t)__cvta_generic_to_shared(sm);                 \
    const uint32_t a_off = ((wm + (lane & 15)) * PITCH + ((lane >> 4) << 3)) * 2;   \
    const uint32_t b_off = ((wn + (lane & 7) + ((lane >> 4) << 3)) * PITCH          \
                            + (((lane >> 3) & 1) << 3)) * 2;                        \
    float acc[4][4][4];                                                             \
    _Pragma("unroll") for (int i = 0; i < 4; i++)                                   \
        _Pragma("unroll") for (int j = 0; j < 4; j++)                               \
            _Pragma("unroll") for (int r = 0; r < 4; r++) acc[i][j][r] = 0.f;       \
    auto load_tiles = [&](int k0, int s) {                                          \
        bf16* As = sm + s * TILEE;                                                  \
        bf16* Bs = sm + (2 + s) * TILEE;                                            \
        _Pragma("unroll") for (int i = 0; i < 4; i++) {                             \
            int id  = tid + i * 256;                                                \
            int row = id >> 3;                                                      \
            int cof = (id & 7) << 3;                                                \
            CP16((uint32_t)__cvta_generic_to_shared(As + row * PITCH + cof),        \
                 (A) + (size_t)(bm + row) * (K) + k0 + cof);                        \
            CP16((uint32_t)__cvta_generic_to_shared(Bs + row * PITCH + cof),        \
                 (B) + (size_t)(bn + row) * (K) + k0 + cof);                        \
        }                                                                           \
    };                                                                              \
    load_tiles(0, 0);                                                               \
    CP_COMMIT();                                                                    \
    int s = 0;                                                                      \
    _Pragma("unroll 1") for (int it = 0; it < (K) / 64; it++) {                     \
        CP_WAIT(0);                                                                 \
        __syncthreads();                                                            \
        if (it + 1 < (K) / 64) { load_tiles((it + 1) << 6, s ^ 1); CP_COMMIT(); }   \
        const uint32_t As_u = smem_u + s * (TILEE * 2);                             \
        const uint32_t Bs_u = smem_u + (2 + s) * (TILEE * 2);                       \
        _Pragma("unroll") for (int ks = 0; ks < 4; ks++) {                          \
            const uint32_t kadd = ks * 32;                                          \
            uint32_t a[4][4], b[4][2];                                              \
            _Pragma("unroll") for (int mt = 0; mt < 4; mt++)                        \
                ldsm_x4(a[mt], As_u + a_off + mt * (16 * PITCH * 2) + kadd);        \
            _Pragma("unroll") for (int p = 0; p < 2; p++) {                         \
                uint32_t r[4];                                                      \
                ldsm_x4(r, Bs_u + b_off + p * (16 * PITCH * 2) + kadd);             \
                b[2*p][0]   = r[0]; b[2*p][1]   = r[1];                             \
                b[2*p+1][0] = r[2]; b[2*p+1][1] = r[3];                             \
            }                                                                       \
            _Pragma("unroll") for (int mt = 0; mt < 4; mt++)                        \
                _Pragma("unroll") for (int nt = 0; nt < 4; nt++)                    \
                    mma_bf16(acc[mt][nt], a[mt], b[nt]);                            \
        }                                                                           \
        s ^= 1;                                                                     \
    }

// ================= fused QKV projection =================
__global__ __launch_bounds__(256, 2)
void qkv_kernel(const bf16* __restrict__ ht, float att_scale,
                const float* __restrict__ bq, const float* __restrict__ bk,
                const float* __restrict__ bv)
{
    extern __shared__ bf16 sm[];
    const int which = blockIdx.z >> 2;   // 0 q, 1 k, 2 v
    const int nb    = blockIdx.z & 3;
    const bf16* A = ht + (size_t)nb * CL;
    const bf16* B = (which == 0) ? g_wq : (which == 1) ? g_wk : g_wv;
    const float* bias = (which == 0) ? bq : (which == 1) ? bk : bv;

    const int tid = threadIdx.x;
    const int bm = blockIdx.y * BM;
    const int bn = blockIdx.x * BN;
    const int lane = tid & 31;
    const int warp = tid >> 5;
    const int wm   = (warp >> 2) << 6;
    const int wn   = (warp & 3) << 5;
    const int gid  = lane >> 2;
    const int tig  = lane & 3;

    GEMM_MAINLOOP(A, B, C_DIM)

    if (which <= 1) {
        const float scl = (which == 0) ? att_scale : 1.f;
        bf16* C = ((which == 0) ? g_q : g_k) + (size_t)nb * CL;
        #pragma unroll
        for (int mt = 0; mt < 4; mt++) {
            #pragma unroll
            for (int nt = 0; nt < 4; nt++) {
                int m0 = bm + wm + mt * 16 + gid;
                int n0 = bn + wn + nt * 8 + 2 * tig;
                float b0 = bias[n0], b1 = bias[n0 + 1];
                float d0 = (acc[mt][nt][0] + b0) * scl;
                float d1 = (acc[mt][nt][1] + b1) * scl;
                float d2 = (acc[mt][nt][2] + b0) * scl;
                float d3 = (acc[mt][nt][3] + b1) * scl;
                *(__nv_bfloat162*)&C[(size_t)m0 * C_DIM + n0]       = __floats2bfloat162_rn(d0, d1);
                *(__nv_bfloat162*)&C[(size_t)(m0 + 8) * C_DIM + n0] = __floats2bfloat162_rn(d2, d3);
            }
        }
    } else {
        // v: transposed store to [C, L] via smem staging
        bf16* smh = sm;
        __syncthreads();
        #pragma unroll
        for (int mt = 0; mt < 4; mt++) {
            #pragma unroll
            for (int nt = 0; nt < 4; nt++) {
                int ml = wm + mt * 16 + gid;
                int nl = wn + nt * 8 + 2 * tig;
                int n0 = bn + nl;
                float b0 = bias[n0], b1 = bias[n0 + 1];
                smh[nl * 136 + ml]           = __float2bfloat16(acc[mt][nt][0] + b0);
                smh[(nl + 1) * 136 + ml]     = __float2bfloat16(acc[mt][nt][1] + b1);
                smh[nl * 136 + ml + 8]       = __float2bfloat16(acc[mt][nt][2] + b0);
                smh[(nl + 1) * 136 + ml + 8] = __float2bfloat16(acc[mt][nt][3] + b1);
            }
        }
        __syncthreads();
        bf16* C = g_v + (size_t)nb * CL;
        #pragma unroll
        for (int i = 0; i < 8; i++) {
            int idx = tid + i * 256;
            int row = idx >> 4;
            int m = (idx & 15) << 3;
            uint4 v = *(uint4*)&smh[row * 136 + m];
            *(uint4*)&C[(size_t)(bn + row) * L_DIM + bm + m] = v;
        }
    }
}

// ================= scores: P = exp(q k^T), bf16, + partial row sums =================
__global__ __launch_bounds__(256, 2)
void scores_kernel()
{
    extern __shared__ bf16 sm[];
    const int nb = blockIdx.z;
    const bf16* A = g_q + (size_t)nb * CL;
    const bf16* B = g_k + (size_t)nb * CL;
    bf16* C = g_p + (size_t)nb * LL;

    const int tid = threadIdx.x;
    const int bm = blockIdx.y * BM;
    const int bn = blockIdx.x * BN;
    const int lane = tid & 31;
    const int warp = tid >> 5;
    const int wm   = (warp >> 2) << 6;
    const int wn   = (warp & 3) << 5;
    const int gid  = lane >> 2;
    const int tig  = lane & 3;

    GEMM_MAINLOOP(A, B, C_DIM)

    // epilogue: exp + bf16 store + per-row partial sums (warp covers 32 cols)
    float* part = (float*)sm;           // [4][128]
    __syncthreads();                    // mainloop smem reads done
    #pragma unroll
    for (int mt = 0; mt < 4; mt++) {
        int m0 = bm + wm + mt * 16 + gid;
        float sA = 0.f, sB = 0.f;
        #pragma unroll
        for (int nt = 0; nt < 4; nt++) {
            int n0 = bn + wn + nt * 8 + 2 * tig;
            float e0 = __expf(acc[mt][nt][0]);
            float e1 = __expf(acc[mt][nt][1]);
            float e2 = __expf(acc[mt][nt][2]);
            float e3 = __expf(acc[mt][nt][3]);
            sA += e0 + e1; sB += e2 + e3;
            *(__nv_bfloat162*)&C[(size_t)m0 * L_DIM + n0]       = __floats2bfloat162_rn(e0, e1);
            *(__nv_bfloat162*)&C[(size_t)(m0 + 8) * L_DIM + n0] = __floats2bfloat162_rn(e2, e3);
        }
        sA += __shfl_xor_sync(0xffffffffu, sA, 1);
        sA += __shfl_xor_sync(0xffffffffu, sA, 2);
        sB += __shfl_xor_sync(0xffffffffu, sB, 1);
        sB += __shfl_xor_sync(0xffffffffu, sB, 2);
        if (tig == 0) {
            part[(warp & 3) * 128 + wm + mt * 16 + gid]     = sA;
            part[(warp & 3) * 128 + wm + mt * 16 + gid + 8] = sB;
        }
    }
    __syncthreads();
    if (tid < 128) {
        float sv = part[tid] + part[128 + tid] + part[256 + tid] + part[384 + tid];
        g_psum[((size_t)nb * L_DIM + bm + tid) * 32 + blockIdx.x] = sv;
    }
}

// ================= rowsum reduce =================
__global__ void rowsum_kernel()
{
    int r = blockIdx.x * 256 + threadIdx.x;    // 16384 rows
    const float* p = g_psum + (size_t)r * 32;
    float sv = 0.f;
    #pragma unroll
    for (int i = 0; i < 32; i++) sv += p[i];
    g_rowsum[r] = sv;
}

// ================= AV: O = (P V^T) / rowsum, bf16 [L, C] =================
__global__ __launch_bounds__(256, 2)
void av_kernel()
{
    extern __shared__ bf16 sm[];
    __shared__ float sinv[128];
    const int nb = blockIdx.z;
    const bf16* A = g_p + (size_t)nb * LL;
    const bf16* B = g_v + (size_t)nb * CL;
    bf16* C = g_o + (size_t)nb * CL;

    const int tid = threadIdx.x;
    const int bm = blockIdx.y * BM;
    const int bn = blockIdx.x * BN;
    const int lane = tid & 31;
    const int warp = tid >> 5;
    const int wm   = (warp >> 2) << 6;
    const int wn   = (warp & 3) << 5;
    const int gid  = lane >> 2;
    const int tig  = lane & 3;

    if (tid < 128) sinv[tid] = 1.f / g_rowsum[(size_t)nb * L_DIM + bm + tid];

    GEMM_MAINLOOP(A, B, L_DIM)

    #pragma unroll
    for (int mt = 0; mt < 4; mt++) {
        int ml = wm + mt * 16 + gid;
        int m0 = bm + ml;
        float i0 = sinv[ml], i1 = sinv[ml + 8];
        #pragma unroll
        for (int nt = 0; nt < 4; nt++) {
            int n0 = bn + wn + nt * 8 + 2 * tig;
            *(__nv_bfloat162*)&C[(size_t)m0 * C_DIM + n0] =
                __floats2bfloat162_rn(acc[mt][nt][0] * i0, acc[mt][nt][1] * i0);
            *(__nv_bfloat162*)&C[(size_t)(m0 + 8) * C_DIM + n0] =
                __floats2bfloat162_rn(acc[mt][nt][2] * i1, acc[mt][nt][3] * i1);
        }
    }
}

// ================= final projection: out = (O x wo^T)^T + bo + x =================
__global__ __launch_bounds__(256, 2)
void final_kernel(float* __restrict__ Cg, const float* __restrict__ bias,
                  const float* __restrict__ resg)
{
    extern __shared__ bf16 sm[];
    const int tid = threadIdx.x;
    const int bm = blockIdx.y * BM;
    const int bn = blockIdx.x * BN;
    const bf16* A = g_o + (size_t)blockIdx.z * CL;
    const bf16* B = g_wo;
    const float* R = resg + (size_t)blockIdx.z * CL;
    float* C = Cg + (size_t)blockIdx.z * CL;

    const int lane = tid & 31;
    const int warp = tid >> 5;
    const int wm   = (warp >> 2) << 6;
    const int wn   = (warp & 3) << 5;
    const int gid  = lane >> 2;
    const int tig  = lane & 3;

    GEMM_MAINLOOP(A, B, C_DIM)

    float* smf = (float*)sm;
    __syncthreads();
    #pragma unroll
    for (int mt = 0; mt < 4; mt++) {
        #pragma unroll
        for (int nt = 0; nt < 4; nt++) {
            int ml = wm + mt * 16 + gid;
            int nl = wn + nt * 8 + 2 * tig;
            int n0 = bn + nl;
            float b0 = bias[n0], b1 = bias[n0 + 1];
            smf[nl * 132 + ml]           = acc[mt][nt][0] + b0;
            smf[(nl + 1) * 132 + ml]     = acc[mt][nt][1] + b1;
            smf[nl * 132 + ml + 8]       = acc[mt][nt][2] + b0;
            smf[(nl + 1) * 132 + ml + 8] = acc[mt][nt][3] + b1;
        }
    }
    __syncthreads();
    #pragma unroll
    for (int i = 0; i < 16; i++) {
        int idx = tid + i * 256;
        int row = idx >> 5;
        int m = (idx & 31) << 2;
        size_t gidx = (size_t)(bn + row) * L_DIM + bm + m;
        float4 v = *(float4*)&smf[row * 132 + m];
        float4 r4 = *(const float4*)&R[gidx];
        v.x += r4.x; v.y += r4.y; v.z += r4.z; v.w += r4.w;
        *(float4*)&C[gidx] = v;
    }
}

// ---------------- host launch ----------------
extern "C" void kernel_launch(void* const* d_in, const int* in_sizes, int n_in,
                              void* d_out, int out_size)
{
    const float* x        = (const float*)d_in[0];
    const float* gn_scale = (const float*)d_in[1];
    const float* gn_bias  = (const float*)d_in[2];
    const float* wq = (const float*)d_in[3];
    const float* bq = (const float*)d_in[4];
    const float* wk = (const float*)d_in[5];
    const float* bk = (const float*)d_in[6];
    const float* wv = (const float*)d_in[7];
    const float* bv = (const float*)d_in[8];
    const float* wo = (const float*)d_in[9];
    const float* bo = (const float*)d_in[10];
    float* out = (float*)d_out;

    static bf16* p_ht = nullptr;
    if (!p_ht) {
        cudaGetSymbolAddress((void**)&p_ht, g_ht);
        cudaFuncSetAttribute(qkv_kernel,    cudaFuncAttributeMaxDynamicSharedMemorySize, SMEM_BYTES);
        cudaFuncSetAttribute(scores_kernel, cudaFuncAttributeMaxDynamicSharedMemorySize, SMEM_BYTES);
        cudaFuncSetAttribute(av_kernel,     cudaFuncAttributeMaxDynamicSharedMemorySize, SMEM_BYTES);
        cudaFuncSetAttribute(final_kernel,  cudaFuncAttributeMaxDynamicSharedMemorySize, SMEM_BYTES);
    }

    const float att_scale = 0.044194173824159216f;   // 512^-0.5

    cvt_w_kernel<<<(C_DIM * C_DIM) / 256, 256>>>(wq, wk, wv, wo);
    gn_kernel<<<N_BATCH * NGROUP, 512>>>(x, gn_scale, gn_bias, p_ht);

    dim3 gq(C_DIM / BN, L_DIM / BM, 3 * N_BATCH);   // (4, 32, 12)
    qkv_kernel<<<gq, 256, SMEM_BYTES>>>(p_ht, att_scale, bq, bk, bv);

    dim3 gs(L_DIM / BN, L_DIM / BM, N_BATCH);       // (32, 32, 4)
    scores_kernel<<<gs, 256, SMEM_BYTES>>>();

    rowsum_kernel<<<(N_BATCH * L_DIM) / 256, 256>>>();

    dim3 ga(C_DIM / BN, L_DIM / BM, N_BATCH);       // (4, 32, 4)
    av_kernel<<<ga, 256, SMEM_BYTES>>>();

    final_kernel<<<ga, 256, SMEM_BYTES>>>(out, bo, x);
}